// round 2
// baseline (speedup 1.0000x reference)
#include <cuda_runtime.h>

#define Bn  2
#define Tn  2048
#define Dn  1024
#define Hn  16
#define DKn 64
#define Mn  (Bn*Tn)   // 4096
#define Nqkv (3*Dn)   // 3072

// Scratch (device globals — no allocations allowed)
__device__ float g_Q[Bn*Hn*Tn*DKn];   // [B,H,T,DK], pre-scaled by 1/8
__device__ float g_K[Bn*Hn*Tn*DKn];
__device__ float g_V[Bn*Hn*Tn*DKn];
__device__ float g_A[Bn*Tn*Dn];       // attention output [B,T,D]

// ---------------------------------------------------------------------------
// Kernel 1: QKV = x @ w_qkv^T + b_qkv, fused RoPE on q/k, fused 1/sqrt(DK)
// into q, scattered into [B,H,T,DK] scratch.
// Tiles: 128x128x8, 256 threads, 8x8 per thread.
// ---------------------------------------------------------------------------
__global__ __launch_bounds__(256) void qkv_rope_kernel(
    const float* __restrict__ x, const float* __restrict__ w,
    const float* __restrict__ bias, const float* __restrict__ fc,
    const float* __restrict__ fs)
{
    __shared__ float As[8][132];
    __shared__ float Bs[8][132];
    const int tid = threadIdx.x;
    const int m0 = blockIdx.y * 128;
    const int n0 = blockIdx.x * 128;
    const int ty = tid >> 4, tx = tid & 15;
    const int lrow = tid >> 1;
    const int lcol = (tid & 1) << 2;

    float acc[8][8];
    #pragma unroll
    for (int i = 0; i < 8; i++)
        #pragma unroll
        for (int j = 0; j < 8; j++) acc[i][j] = 0.f;

    const float* aptr = x + (m0 + lrow) * Dn + lcol;
    const float* bptr = w + (n0 + lrow) * Dn + lcol;

    for (int k0 = 0; k0 < Dn; k0 += 8) {
        float4 av = *(const float4*)(aptr + k0);
        float4 bv = *(const float4*)(bptr + k0);
        __syncthreads();
        As[lcol+0][lrow] = av.x; As[lcol+1][lrow] = av.y;
        As[lcol+2][lrow] = av.z; As[lcol+3][lrow] = av.w;
        Bs[lcol+0][lrow] = bv.x; Bs[lcol+1][lrow] = bv.y;
        Bs[lcol+2][lrow] = bv.z; Bs[lcol+3][lrow] = bv.w;
        __syncthreads();
        #pragma unroll
        for (int kk = 0; kk < 8; kk++) {
            float a[8], b[8];
            *(float4*)(a)     = *(const float4*)&As[kk][ty*8];
            *(float4*)(a + 4) = *(const float4*)&As[kk][ty*8 + 4];
            *(float4*)(b)     = *(const float4*)&Bs[kk][tx*8];
            *(float4*)(b + 4) = *(const float4*)&Bs[kk][tx*8 + 4];
            #pragma unroll
            for (int i = 0; i < 8; i++)
                #pragma unroll
                for (int j = 0; j < 8; j++)
                    acc[i][j] += a[i] * b[j];
        }
    }

    const int nBase  = n0 + tx * 8;
    const int region = n0 >> 10;            // 0=q, 1=k, 2=v (128 | 1024)
    const int h = (nBase & 1023) >> 6;
    const int d = nBase & 63;
    float* dst = (region == 0) ? g_Q : (region == 1) ? g_K : g_V;

    float bb[8];
    #pragma unroll
    for (int j = 0; j < 8; j++) bb[j] = bias[nBase + j];

    #pragma unroll
    for (int i = 0; i < 8; i++) {
        int m  = m0 + ty * 8 + i;
        int bi = m >> 11;       // / 2048
        int t  = m & 2047;
        float v[8];
        #pragma unroll
        for (int j = 0; j < 8; j++) v[j] = acc[i][j] + bb[j];
        if (region < 2) {
            int p0 = d >> 1;
            #pragma unroll
            for (int jp = 0; jp < 4; jp++) {
                float c = fc[t * (DKn/2) + p0 + jp];
                float s = fs[t * (DKn/2) + p0 + jp];
                float re = v[2*jp], im = v[2*jp + 1];
                v[2*jp]     = re * c - im * s;
                v[2*jp + 1] = re * s + im * c;
            }
            if (region == 0) {
                #pragma unroll
                for (int j = 0; j < 8; j++) v[j] *= 0.125f;  // 1/sqrt(64)
            }
        }
        int base = ((bi * Hn + h) * Tn + t) * DKn + d;
        *(float4*)&dst[base]     = make_float4(v[0], v[1], v[2], v[3]);
        *(float4*)&dst[base + 4] = make_float4(v[4], v[5], v[6], v[7]);
    }
}

// ---------------------------------------------------------------------------
// Kernel 2: causal flash attention, fp32. BQ = BK = 64, 256 threads,
// 4x4 register tiles for S and O. Online softmax, 16-lane shfl reductions.
// Smem: Q^T [64dk][64q], K^T [64dk][68] (pad; aliased as P [64q][68]),
//       V [64k][64dk].  Total 50176 B (dynamic).
// ---------------------------------------------------------------------------
#define SMEM_ATTN_FLOATS (64*64 + 64*68 + 64*64)
#define SMEM_ATTN_BYTES  (SMEM_ATTN_FLOATS * 4)

__global__ __launch_bounds__(256) void attn_kernel()
{
    extern __shared__ float sm[];
    float* Qst = sm;                       // [dk][q]   stride 64
    float* Kst = sm + 64*64;               // [dk][k]   stride 68 ; alias P [q][k] stride 68
    float* Vs  = sm + 64*64 + 64*68;       // [k][dk]   stride 64

    const int tid = threadIdx.x;
    const int ty = tid >> 4, tx = tid & 15;
    const int qt = blockIdx.x;             // 0..31
    const int bh = blockIdx.y;             // 0..31
    const int q0 = qt * 64;

    const float* Qg = g_Q + (bh * Tn + q0) * DKn;
    const float* Kg = g_K + bh * Tn * DKn;
    const float* Vg = g_V + bh * Tn * DKn;

    // Load Q tile transposed (one-time)
    #pragma unroll
    for (int s = 0; s < 4; s++) {
        int idx = tid + 256 * s;
        int r = idx >> 4;
        int c = (idx & 15) << 2;
        float4 v = *(const float4*)&Qg[r * DKn + c];
        Qst[(c+0)*64 + r] = v.x;
        Qst[(c+1)*64 + r] = v.y;
        Qst[(c+2)*64 + r] = v.z;
        Qst[(c+3)*64 + r] = v.w;
    }

    float O[4][4];
    float mrow[4], lrow[4];
    #pragma unroll
    for (int i = 0; i < 4; i++) {
        mrow[i] = -1e30f; lrow[i] = 0.f;
        #pragma unroll
        for (int j = 0; j < 4; j++) O[i][j] = 0.f;
    }

    for (int kt = 0; kt <= qt; kt++) {
        const int k0 = kt * 64;
        __syncthreads();   // previous PV done (and Q stores on first iter)
        #pragma unroll
        for (int s = 0; s < 4; s++) {
            int idx = tid + 256 * s;
            int r = idx >> 4;
            int c = (idx & 15) << 2;
            float4 kv = *(const float4*)&Kg[(k0 + r) * DKn + c];
            Kst[(c+0)*68 + r] = kv.x;
            Kst[(c+1)*68 + r] = kv.y;
            Kst[(c+2)*68 + r] = kv.z;
            Kst[(c+3)*68 + r] = kv.w;
            float4 vv = *(const float4*)&Vg[(k0 + r) * DKn + c];
            *(float4*)&Vs[r * 64 + c] = vv;
        }
        __syncthreads();

        // S = Q K^T (q already scaled)
        float S[4][4];
        #pragma unroll
        for (int i = 0; i < 4; i++)
            #pragma unroll
            for (int j = 0; j < 4; j++) S[i][j] = 0.f;

        #pragma unroll 16
        for (int kk = 0; kk < 64; kk++) {
            float4 a4 = *(const float4*)&Qst[kk*64 + ty*4];
            float4 b4 = *(const float4*)&Kst[kk*68 + tx*4];
            float a[4] = {a4.x, a4.y, a4.z, a4.w};
            float b[4] = {b4.x, b4.y, b4.z, b4.w};
            #pragma unroll
            for (int i = 0; i < 4; i++)
                #pragma unroll
                for (int j = 0; j < 4; j++)
                    S[i][j] += a[i] * b[j];
        }

        if (kt == qt) {   // diagonal tile: mask k > q
            #pragma unroll
            for (int i = 0; i < 4; i++)
                #pragma unroll
                for (int j = 0; j < 4; j++)
                    if (tx*4 + j > ty*4 + i) S[i][j] = -1e30f;
        }

        // Online softmax update (row reductions over the 16 tx lanes)
        #pragma unroll
        for (int i = 0; i < 4; i++) {
            float mx = fmaxf(fmaxf(S[i][0], S[i][1]), fmaxf(S[i][2], S[i][3]));
            #pragma unroll
            for (int off = 1; off < 16; off <<= 1)
                mx = fmaxf(mx, __shfl_xor_sync(0xffffffffu, mx, off));
            float mnew  = fmaxf(mrow[i], mx);
            float alpha = __expf(mrow[i] - mnew);
            mrow[i] = mnew;
            float rs = 0.f;
            #pragma unroll
            for (int j = 0; j < 4; j++) { S[i][j] = __expf(S[i][j] - mnew); rs += S[i][j]; }
            #pragma unroll
            for (int off = 1; off < 16; off <<= 1)
                rs += __shfl_xor_sync(0xffffffffu, rs, off);
            lrow[i] = lrow[i] * alpha + rs;
            #pragma unroll
            for (int j = 0; j < 4; j++) O[i][j] *= alpha;
        }

        __syncthreads();   // everyone done reading Kst
        // P -> smem (reuse Kst buffer), layout [q][68]
        #pragma unroll
        for (int i = 0; i < 4; i++)
            *(float4*)&Kst[(ty*4 + i)*68 + tx*4] =
                make_float4(S[i][0], S[i][1], S[i][2], S[i][3]);
        __syncthreads();

        // O += P @ V
        #pragma unroll 16
        for (int k = 0; k < 64; k++) {
            float p[4];
            #pragma unroll
            for (int i = 0; i < 4; i++) p[i] = Kst[(ty*4 + i)*68 + k];
            float4 v4 = *(const float4*)&Vs[k*64 + tx*4];
            float v[4] = {v4.x, v4.y, v4.z, v4.w};
            #pragma unroll
            for (int i = 0; i < 4; i++)
                #pragma unroll
                for (int j = 0; j < 4; j++)
                    O[i][j] += p[i] * v[j];
        }
    }

    // Normalize and write [B,T,D]
    const int bi = bh >> 4;
    const int h  = bh & 15;
    #pragma unroll
    for (int i = 0; i < 4; i++) {
        int t = q0 + ty*4 + i;
        float inv = 1.f / lrow[i];
        *(float4*)&g_A[(bi * Tn + t) * Dn + h * DKn + tx*4] =
            make_float4(O[i][0]*inv, O[i][1]*inv, O[i][2]*inv, O[i][3]*inv);
    }
}

// ---------------------------------------------------------------------------
// Kernel 3: out = g_A @ w_out^T + b_out
// ---------------------------------------------------------------------------
__global__ __launch_bounds__(256) void proj_kernel(
    const float* __restrict__ w, const float* __restrict__ bias,
    float* __restrict__ out)
{
    __shared__ float As[8][132];
    __shared__ float Bs[8][132];
    const int tid = threadIdx.x;
    const int m0 = blockIdx.y * 128;
    const int n0 = blockIdx.x * 128;
    const int ty = tid >> 4, tx = tid & 15;
    const int lrow = tid >> 1;
    const int lcol = (tid & 1) << 2;

    float acc[8][8];
    #pragma unroll
    for (int i = 0; i < 8; i++)
        #pragma unroll
        for (int j = 0; j < 8; j++) acc[i][j] = 0.f;

    const float* aptr = g_A + (m0 + lrow) * Dn + lcol;
    const float* bptr = w   + (n0 + lrow) * Dn + lcol;

    for (int k0 = 0; k0 < Dn; k0 += 8) {
        float4 av = *(const float4*)(aptr + k0);
        float4 bv = *(const float4*)(bptr + k0);
        __syncthreads();
        As[lcol+0][lrow] = av.x; As[lcol+1][lrow] = av.y;
        As[lcol+2][lrow] = av.z; As[lcol+3][lrow] = av.w;
        Bs[lcol+0][lrow] = bv.x; Bs[lcol+1][lrow] = bv.y;
        Bs[lcol+2][lrow] = bv.z; Bs[lcol+3][lrow] = bv.w;
        __syncthreads();
        #pragma unroll
        for (int kk = 0; kk < 8; kk++) {
            float a[8], b[8];
            *(float4*)(a)     = *(const float4*)&As[kk][ty*8];
            *(float4*)(a + 4) = *(const float4*)&As[kk][ty*8 + 4];
            *(float4*)(b)     = *(const float4*)&Bs[kk][tx*8];
            *(float4*)(b + 4) = *(const float4*)&Bs[kk][tx*8 + 4];
            #pragma unroll
            for (int i = 0; i < 8; i++)
                #pragma unroll
                for (int j = 0; j < 8; j++)
                    acc[i][j] += a[i] * b[j];
        }
    }

    const int nBase = n0 + tx * 8;
    float bb[8];
    #pragma unroll
    for (int j = 0; j < 8; j++) bb[j] = bias[nBase + j];

    #pragma unroll
    for (int i = 0; i < 8; i++) {
        int m = m0 + ty * 8 + i;
        float v[8];
        #pragma unroll
        for (int j = 0; j < 8; j++) v[j] = acc[i][j] + bb[j];
        *(float4*)&out[m * Dn + nBase]     = make_float4(v[0], v[1], v[2], v[3]);
        *(float4*)&out[m * Dn + nBase + 4] = make_float4(v[4], v[5], v[6], v[7]);
    }
}

// ---------------------------------------------------------------------------
extern "C" void kernel_launch(void* const* d_in, const int* in_sizes, int n_in,
                              void* d_out, int out_size)
{
    const float* x    = (const float*)d_in[0];
    const float* wqkv = (const float*)d_in[1];
    const float* bqkv = (const float*)d_in[2];
    const float* wout = (const float*)d_in[3];
    const float* bout = (const float*)d_in[4];
    const float* fc   = (const float*)d_in[5];
    const float* fs   = (const float*)d_in[6];
    float* out = (float*)d_out;

    // Not a stream op — safe under graph capture; idempotent.
    cudaFuncSetAttribute(attn_kernel,
                         cudaFuncAttributeMaxDynamicSharedMemorySize,
                         SMEM_ATTN_BYTES);

    qkv_rope_kernel<<<dim3(Nqkv/128, Mn/128), 256>>>(x, wqkv, bqkv, fc, fs);
    attn_kernel<<<dim3(Tn/64, Bn*Hn), 256, SMEM_ATTN_BYTES>>>();
    proj_kernel<<<dim3(Dn/128, Mn/128), 256>>>(wout, bout, out);
}

// round 3
// speedup vs baseline: 1.6963x; 1.6963x over previous
#include <cuda_runtime.h>

#define Bn  2
#define Tn  2048
#define Dn  1024
#define Hn  16
#define DKn 64
#define Mn  (Bn*Tn)   // 4096
#define Nqkv (3*Dn)   // 3072

// Scratch (device globals — no allocations allowed)
__device__ float g_Q[Bn*Hn*Tn*DKn];   // [B,H,T,DK], pre-scaled by 1/8
__device__ float g_K[Bn*Hn*Tn*DKn];
__device__ float g_V[Bn*Hn*Tn*DKn];
__device__ float g_A[Bn*Tn*Dn];       // attention output [B,T,D]

// ---------------------------------------------------------------------------
// tf32 helpers
// ---------------------------------------------------------------------------
__device__ __forceinline__ unsigned f2tf32(float x) {
    unsigned r;
    asm("cvt.rna.tf32.f32 %0, %1;" : "=r"(r) : "f"(x));
    return r;
}

__device__ __forceinline__ void mma_tf32(float* c, const unsigned* a,
                                         unsigned b0, unsigned b1) {
    asm volatile(
        "mma.sync.aligned.m16n8k8.row.col.f32.tf32.tf32.f32 "
        "{%0,%1,%2,%3}, {%4,%5,%6,%7}, {%8,%9}, {%0,%1,%2,%3};\n"
        : "+f"(c[0]), "+f"(c[1]), "+f"(c[2]), "+f"(c[3])
        : "r"(a[0]), "r"(a[1]), "r"(a[2]), "r"(a[3]), "r"(b0), "r"(b1));
}

// Shared GEMM mainloop: acc[2][8][4] += A[128,1024] tile @ B[128,1024] tile^T
// A, B row-major with K contiguous (B rows are output columns).
// Warp layout: warp = 4(m) x 2(n); warp tile 32x64.
// Smem stride 36 => fragment LDS bank == lane (conflict-free).
#define GEMM_MAINLOOP(Aptr, Bptr)                                              \
    {                                                                          \
        const int arow = tid >> 3;                                             \
        const int acol = (tid & 7) * 4;                                        \
        for (int k0 = 0; k0 < Dn; k0 += 32) {                                  \
            __syncthreads();                                                   \
            _Pragma("unroll")                                                  \
            for (int s = 0; s < 4; s++) {                                      \
                int r = arow + 32 * s;                                         \
                float4 av = *(const float4*)&(Aptr)[(m0 + r) * Dn + k0 + acol];\
                float4 wv = *(const float4*)&(Bptr)[(n0 + r) * Dn + k0 + acol];\
                unsigned* pa = &As[r * 36 + acol];                             \
                pa[0] = f2tf32(av.x); pa[1] = f2tf32(av.y);                    \
                pa[2] = f2tf32(av.z); pa[3] = f2tf32(av.w);                    \
                unsigned* pw = &Ws[r * 36 + acol];                             \
                pw[0] = f2tf32(wv.x); pw[1] = f2tf32(wv.y);                    \
                pw[2] = f2tf32(wv.z); pw[3] = f2tf32(wv.w);                    \
            }                                                                  \
            __syncthreads();                                                   \
            _Pragma("unroll")                                                  \
            for (int ks = 0; ks < 32; ks += 8) {                               \
                unsigned afr[2][4];                                            \
                int ar0 = wm * 32 + (lane >> 2);                               \
                _Pragma("unroll")                                              \
                for (int mt = 0; mt < 2; mt++) {                               \
                    int r = ar0 + mt * 16;                                     \
                    afr[mt][0] = As[r * 36 + ks + (lane & 3)];                 \
                    afr[mt][1] = As[(r + 8) * 36 + ks + (lane & 3)];           \
                    afr[mt][2] = As[r * 36 + ks + (lane & 3) + 4];             \
                    afr[mt][3] = As[(r + 8) * 36 + ks + (lane & 3) + 4];       \
                }                                                              \
                _Pragma("unroll")                                              \
                for (int j = 0; j < 8; j++) {                                  \
                    int n = wn * 64 + j * 8 + (lane >> 2);                     \
                    unsigned b0 = Ws[n * 36 + ks + (lane & 3)];                \
                    unsigned b1 = Ws[n * 36 + ks + (lane & 3) + 4];            \
                    mma_tf32(acc[0][j], afr[0], b0, b1);                       \
                    mma_tf32(acc[1][j], afr[1], b0, b1);                       \
                }                                                              \
            }                                                                  \
        }                                                                      \
    }

// ---------------------------------------------------------------------------
// Kernel 1: QKV = x @ w_qkv^T + b_qkv, fused RoPE + 1/8 scale on q (tf32 mma)
// ---------------------------------------------------------------------------
__global__ __launch_bounds__(256) void qkv_mma_kernel(
    const float* __restrict__ x, const float* __restrict__ w,
    const float* __restrict__ bias, const float* __restrict__ fc,
    const float* __restrict__ fs)
{
    __shared__ unsigned As[128 * 36];
    __shared__ unsigned Ws[128 * 36];
    const int tid  = threadIdx.x;
    const int warp = tid >> 5, lane = tid & 31;
    const int wm = warp & 3, wn = warp >> 2;
    const int m0 = blockIdx.y * 128;
    const int n0 = blockIdx.x * 128;

    float acc[2][8][4];
    #pragma unroll
    for (int mt = 0; mt < 2; mt++)
        #pragma unroll
        for (int j = 0; j < 8; j++)
            #pragma unroll
            for (int e = 0; e < 4; e++) acc[mt][j][e] = 0.f;

    GEMM_MAINLOOP(x, w)

    // Epilogue: bias + RoPE (+1/8 on q), scatter into [B,H,T,DK]
    const int region = n0 >> 10;   // whole CTA in one region (128 | 1024)
    float* dst = (region == 0) ? g_Q : (region == 1) ? g_K : g_V;
    const int rbase = m0 + wm * 32 + (lane >> 2);

    #pragma unroll
    for (int j = 0; j < 8; j++) {
        const int n  = n0 + wn * 64 + j * 8 + (lane & 3) * 2;  // even
        const int h  = (n & 1023) >> 6;
        const int d  = n & 63;
        const int p  = d >> 1;
        const float bv0 = bias[n], bv1 = bias[n + 1];
        #pragma unroll
        for (int mt = 0; mt < 2; mt++) {
            #pragma unroll
            for (int half = 0; half < 2; half++) {
                const int r  = rbase + mt * 16 + half * 8;
                const int bi = r >> 11;
                const int t  = r & 2047;
                float re = acc[mt][j][half * 2 + 0] + bv0;
                float im = acc[mt][j][half * 2 + 1] + bv1;
                if (region < 2) {
                    float c = fc[t * (DKn / 2) + p];
                    float s = fs[t * (DKn / 2) + p];
                    float nre = re * c - im * s;
                    float nim = re * s + im * c;
                    re = nre; im = nim;
                    if (region == 0) { re *= 0.125f; im *= 0.125f; }
                }
                *(float2*)&dst[((bi * Hn + h) * Tn + t) * DKn + d] =
                    make_float2(re, im);
            }
        }
    }
}

// ---------------------------------------------------------------------------
// Kernel 3: out = g_A @ w_out^T + b_out (tf32 mma)
// ---------------------------------------------------------------------------
__global__ __launch_bounds__(256) void proj_mma_kernel(
    const float* __restrict__ w, const float* __restrict__ bias,
    float* __restrict__ out)
{
    __shared__ unsigned As[128 * 36];
    __shared__ unsigned Ws[128 * 36];
    const int tid  = threadIdx.x;
    const int warp = tid >> 5, lane = tid & 31;
    const int wm = warp & 3, wn = warp >> 2;
    const int m0 = blockIdx.y * 128;
    const int n0 = blockIdx.x * 128;

    float acc[2][8][4];
    #pragma unroll
    for (int mt = 0; mt < 2; mt++)
        #pragma unroll
        for (int j = 0; j < 8; j++)
            #pragma unroll
            for (int e = 0; e < 4; e++) acc[mt][j][e] = 0.f;

    GEMM_MAINLOOP(g_A, w)

    const int rbase = m0 + wm * 32 + (lane >> 2);
    #pragma unroll
    for (int j = 0; j < 8; j++) {
        const int n = n0 + wn * 64 + j * 8 + (lane & 3) * 2;
        const float bv0 = bias[n], bv1 = bias[n + 1];
        #pragma unroll
        for (int mt = 0; mt < 2; mt++) {
            #pragma unroll
            for (int half = 0; half < 2; half++) {
                const int r = rbase + mt * 16 + half * 8;
                *(float2*)&out[r * Dn + n] =
                    make_float2(acc[mt][j][half * 2 + 0] + bv0,
                                acc[mt][j][half * 2 + 1] + bv1);
            }
        }
    }
}

// ---------------------------------------------------------------------------
// Kernel 2: causal flash attention, fp32 SIMT (unchanged this round)
// ---------------------------------------------------------------------------
#define SMEM_ATTN_FLOATS (64*64 + 64*68 + 64*64)
#define SMEM_ATTN_BYTES  (SMEM_ATTN_FLOATS * 4)

__global__ __launch_bounds__(256) void attn_kernel()
{
    extern __shared__ float sm[];
    float* Qst = sm;                       // [dk][q]   stride 64
    float* Kst = sm + 64*64;               // [dk][k]   stride 68 ; alias P [q][k]
    float* Vs  = sm + 64*64 + 64*68;       // [k][dk]   stride 64

    const int tid = threadIdx.x;
    const int ty = tid >> 4, tx = tid & 15;
    const int qt = blockIdx.x;
    const int bh = blockIdx.y;
    const int q0 = qt * 64;

    const float* Qg = g_Q + (bh * Tn + q0) * DKn;
    const float* Kg = g_K + bh * Tn * DKn;
    const float* Vg = g_V + bh * Tn * DKn;

    #pragma unroll
    for (int s = 0; s < 4; s++) {
        int idx = tid + 256 * s;
        int r = idx >> 4;
        int c = (idx & 15) << 2;
        float4 v = *(const float4*)&Qg[r * DKn + c];
        Qst[(c+0)*64 + r] = v.x;
        Qst[(c+1)*64 + r] = v.y;
        Qst[(c+2)*64 + r] = v.z;
        Qst[(c+3)*64 + r] = v.w;
    }

    float O[4][4];
    float mrow[4], lrow[4];
    #pragma unroll
    for (int i = 0; i < 4; i++) {
        mrow[i] = -1e30f; lrow[i] = 0.f;
        #pragma unroll
        for (int j = 0; j < 4; j++) O[i][j] = 0.f;
    }

    for (int kt = 0; kt <= qt; kt++) {
        const int k0 = kt * 64;
        __syncthreads();
        #pragma unroll
        for (int s = 0; s < 4; s++) {
            int idx = tid + 256 * s;
            int r = idx >> 4;
            int c = (idx & 15) << 2;
            float4 kv = *(const float4*)&Kg[(k0 + r) * DKn + c];
            Kst[(c+0)*68 + r] = kv.x;
            Kst[(c+1)*68 + r] = kv.y;
            Kst[(c+2)*68 + r] = kv.z;
            Kst[(c+3)*68 + r] = kv.w;
            float4 vv = *(const float4*)&Vg[(k0 + r) * DKn + c];
            *(float4*)&Vs[r * 64 + c] = vv;
        }
        __syncthreads();

        float S[4][4];
        #pragma unroll
        for (int i = 0; i < 4; i++)
            #pragma unroll
            for (int j = 0; j < 4; j++) S[i][j] = 0.f;

        #pragma unroll 16
        for (int kk = 0; kk < 64; kk++) {
            float4 a4 = *(const float4*)&Qst[kk*64 + ty*4];
            float4 b4 = *(const float4*)&Kst[kk*68 + tx*4];
            float a[4] = {a4.x, a4.y, a4.z, a4.w};
            float b[4] = {b4.x, b4.y, b4.z, b4.w};
            #pragma unroll
            for (int i = 0; i < 4; i++)
                #pragma unroll
                for (int j = 0; j < 4; j++)
                    S[i][j] += a[i] * b[j];
        }

        if (kt == qt) {
            #pragma unroll
            for (int i = 0; i < 4; i++)
                #pragma unroll
                for (int j = 0; j < 4; j++)
                    if (tx*4 + j > ty*4 + i) S[i][j] = -1e30f;
        }

        #pragma unroll
        for (int i = 0; i < 4; i++) {
            float mx = fmaxf(fmaxf(S[i][0], S[i][1]), fmaxf(S[i][2], S[i][3]));
            #pragma unroll
            for (int off = 1; off < 16; off <<= 1)
                mx = fmaxf(mx, __shfl_xor_sync(0xffffffffu, mx, off));
            float mnew  = fmaxf(mrow[i], mx);
            float alpha = __expf(mrow[i] - mnew);
            mrow[i] = mnew;
            float rs = 0.f;
            #pragma unroll
            for (int j = 0; j < 4; j++) { S[i][j] = __expf(S[i][j] - mnew); rs += S[i][j]; }
            #pragma unroll
            for (int off = 1; off < 16; off <<= 1)
                rs += __shfl_xor_sync(0xffffffffu, rs, off);
            lrow[i] = lrow[i] * alpha + rs;
            #pragma unroll
            for (int j = 0; j < 4; j++) O[i][j] *= alpha;
        }

        __syncthreads();
        #pragma unroll
        for (int i = 0; i < 4; i++)
            *(float4*)&Kst[(ty*4 + i)*68 + tx*4] =
                make_float4(S[i][0], S[i][1], S[i][2], S[i][3]);
        __syncthreads();

        #pragma unroll 16
        for (int k = 0; k < 64; k++) {
            float p[4];
            #pragma unroll
            for (int i = 0; i < 4; i++) p[i] = Kst[(ty*4 + i)*68 + k];
            float4 v4 = *(const float4*)&Vs[k*64 + tx*4];
            float v[4] = {v4.x, v4.y, v4.z, v4.w};
            #pragma unroll
            for (int i = 0; i < 4; i++)
                #pragma unroll
                for (int j = 0; j < 4; j++)
                    O[i][j] += p[i] * v[j];
        }
    }

    const int bi = bh >> 4;
    const int h  = bh & 15;
    #pragma unroll
    for (int i = 0; i < 4; i++) {
        int t = q0 + ty*4 + i;
        float inv = 1.f / lrow[i];
        *(float4*)&g_A[(bi * Tn + t) * Dn + h * DKn + tx*4] =
            make_float4(O[i][0]*inv, O[i][1]*inv, O[i][2]*inv, O[i][3]*inv);
    }
}

// ---------------------------------------------------------------------------
extern "C" void kernel_launch(void* const* d_in, const int* in_sizes, int n_in,
                              void* d_out, int out_size)
{
    const float* x    = (const float*)d_in[0];
    const float* wqkv = (const float*)d_in[1];
    const float* bqkv = (const float*)d_in[2];
    const float* wout = (const float*)d_in[3];
    const float* bout = (const float*)d_in[4];
    const float* fc   = (const float*)d_in[5];
    const float* fs   = (const float*)d_in[6];
    float* out = (float*)d_out;

    cudaFuncSetAttribute(attn_kernel,
                         cudaFuncAttributeMaxDynamicSharedMemorySize,
                         SMEM_ATTN_BYTES);

    qkv_mma_kernel<<<dim3(Nqkv/128, Mn/128), 256>>>(x, wqkv, bqkv, fc, fs);
    attn_kernel<<<dim3(Tn/64, Bn*Hn), 256, SMEM_ATTN_BYTES>>>();
    proj_mma_kernel<<<dim3(Dn/128, Mn/128), 256>>>(wout, bout, out);
}

// round 4
// speedup vs baseline: 3.3503x; 1.9750x over previous
#include <cuda_runtime.h>

#define Bn  2
#define Tn  2048
#define Dn  1024
#define Hn  16
#define DKn 64
#define Mn  (Bn*Tn)   // 4096
#define Nqkv (3*Dn)   // 3072

// Scratch (device globals — no allocations allowed)
__device__ float g_Q[Bn*Hn*Tn*DKn];   // [B,H,T,DK], pre-scaled by 1/8
__device__ float g_K[Bn*Hn*Tn*DKn];
__device__ float g_V[Bn*Hn*Tn*DKn];
__device__ float g_A[Bn*Tn*Dn];       // attention output [B,T,D]

// ---------------------------------------------------------------------------
// tf32 helpers
// ---------------------------------------------------------------------------
__device__ __forceinline__ unsigned f2tf32(float x) {
    unsigned r;
    asm("cvt.rna.tf32.f32 %0, %1;" : "=r"(r) : "f"(x));
    return r;
}

__device__ __forceinline__ void mma_tf32(float* c, const unsigned* a,
                                         unsigned b0, unsigned b1) {
    asm volatile(
        "mma.sync.aligned.m16n8k8.row.col.f32.tf32.tf32.f32 "
        "{%0,%1,%2,%3}, {%4,%5,%6,%7}, {%8,%9}, {%0,%1,%2,%3};\n"
        : "+f"(c[0]), "+f"(c[1]), "+f"(c[2]), "+f"(c[3])
        : "r"(a[0]), "r"(a[1]), "r"(a[2]), "r"(a[3]), "r"(b0), "r"(b1));
}

// Shared GEMM mainloop (unchanged from round 3)
#define GEMM_MAINLOOP(Aptr, Bptr)                                              \
    {                                                                          \
        const int arow = tid >> 3;                                             \
        const int acol = (tid & 7) * 4;                                        \
        for (int k0 = 0; k0 < Dn; k0 += 32) {                                  \
            __syncthreads();                                                   \
            _Pragma("unroll")                                                  \
            for (int s = 0; s < 4; s++) {                                      \
                int r = arow + 32 * s;                                         \
                float4 av = *(const float4*)&(Aptr)[(m0 + r) * Dn + k0 + acol];\
                float4 wv = *(const float4*)&(Bptr)[(n0 + r) * Dn + k0 + acol];\
                unsigned* pa = &As[r * 36 + acol];                             \
                pa[0] = f2tf32(av.x); pa[1] = f2tf32(av.y);                    \
                pa[2] = f2tf32(av.z); pa[3] = f2tf32(av.w);                    \
                unsigned* pw = &Ws[r * 36 + acol];                             \
                pw[0] = f2tf32(wv.x); pw[1] = f2tf32(wv.y);                    \
                pw[2] = f2tf32(wv.z); pw[3] = f2tf32(wv.w);                    \
            }                                                                  \
            __syncthreads();                                                   \
            _Pragma("unroll")                                                  \
            for (int ks = 0; ks < 32; ks += 8) {                               \
                unsigned afr[2][4];                                            \
                int ar0 = wm * 32 + (lane >> 2);                               \
                _Pragma("unroll")                                              \
                for (int mt = 0; mt < 2; mt++) {                               \
                    int r = ar0 + mt * 16;                                     \
                    afr[mt][0] = As[r * 36 + ks + (lane & 3)];                 \
                    afr[mt][1] = As[(r + 8) * 36 + ks + (lane & 3)];           \
                    afr[mt][2] = As[r * 36 + ks + (lane & 3) + 4];             \
                    afr[mt][3] = As[(r + 8) * 36 + ks + (lane & 3) + 4];       \
                }                                                              \
                _Pragma("unroll")                                              \
                for (int j = 0; j < 8; j++) {                                  \
                    int n = wn * 64 + j * 8 + (lane >> 2);                     \
                    unsigned b0 = Ws[n * 36 + ks + (lane & 3)];                \
                    unsigned b1 = Ws[n * 36 + ks + (lane & 3) + 4];            \
                    mma_tf32(acc[0][j], afr[0], b0, b1);                       \
                    mma_tf32(acc[1][j], afr[1], b0, b1);                       \
                }                                                              \
            }                                                                  \
        }                                                                      \
    }

// ---------------------------------------------------------------------------
// Kernel 1: QKV = x @ w_qkv^T + b_qkv, fused RoPE + 1/8 scale on q (tf32 mma)
// ---------------------------------------------------------------------------
__global__ __launch_bounds__(256) void qkv_mma_kernel(
    const float* __restrict__ x, const float* __restrict__ w,
    const float* __restrict__ bias, const float* __restrict__ fc,
    const float* __restrict__ fs)
{
    __shared__ unsigned As[128 * 36];
    __shared__ unsigned Ws[128 * 36];
    const int tid  = threadIdx.x;
    const int warp = tid >> 5, lane = tid & 31;
    const int wm = warp & 3, wn = warp >> 2;
    const int m0 = blockIdx.y * 128;
    const int n0 = blockIdx.x * 128;

    float acc[2][8][4];
    #pragma unroll
    for (int mt = 0; mt < 2; mt++)
        #pragma unroll
        for (int j = 0; j < 8; j++)
            #pragma unroll
            for (int e = 0; e < 4; e++) acc[mt][j][e] = 0.f;

    GEMM_MAINLOOP(x, w)

    const int region = n0 >> 10;
    float* dst = (region == 0) ? g_Q : (region == 1) ? g_K : g_V;
    const int rbase = m0 + wm * 32 + (lane >> 2);

    #pragma unroll
    for (int j = 0; j < 8; j++) {
        const int n  = n0 + wn * 64 + j * 8 + (lane & 3) * 2;
        const int h  = (n & 1023) >> 6;
        const int d  = n & 63;
        const int p  = d >> 1;
        const float bv0 = bias[n], bv1 = bias[n + 1];
        #pragma unroll
        for (int mt = 0; mt < 2; mt++) {
            #pragma unroll
            for (int half = 0; half < 2; half++) {
                const int r  = rbase + mt * 16 + half * 8;
                const int bi = r >> 11;
                const int t  = r & 2047;
                float re = acc[mt][j][half * 2 + 0] + bv0;
                float im = acc[mt][j][half * 2 + 1] + bv1;
                if (region < 2) {
                    float c = fc[t * (DKn / 2) + p];
                    float s = fs[t * (DKn / 2) + p];
                    float nre = re * c - im * s;
                    float nim = re * s + im * c;
                    re = nre; im = nim;
                    if (region == 0) { re *= 0.125f; im *= 0.125f; }
                }
                *(float2*)&dst[((bi * Hn + h) * Tn + t) * DKn + d] =
                    make_float2(re, im);
            }
        }
    }
}

// ---------------------------------------------------------------------------
// Kernel 3: out = g_A @ w_out^T + b_out (tf32 mma)
// ---------------------------------------------------------------------------
__global__ __launch_bounds__(256) void proj_mma_kernel(
    const float* __restrict__ w, const float* __restrict__ bias,
    float* __restrict__ out)
{
    __shared__ unsigned As[128 * 36];
    __shared__ unsigned Ws[128 * 36];
    const int tid  = threadIdx.x;
    const int warp = tid >> 5, lane = tid & 31;
    const int wm = warp & 3, wn = warp >> 2;
    const int m0 = blockIdx.y * 128;
    const int n0 = blockIdx.x * 128;

    float acc[2][8][4];
    #pragma unroll
    for (int mt = 0; mt < 2; mt++)
        #pragma unroll
        for (int j = 0; j < 8; j++)
            #pragma unroll
            for (int e = 0; e < 4; e++) acc[mt][j][e] = 0.f;

    GEMM_MAINLOOP(g_A, w)

    const int rbase = m0 + wm * 32 + (lane >> 2);
    #pragma unroll
    for (int j = 0; j < 8; j++) {
        const int n = n0 + wn * 64 + j * 8 + (lane & 3) * 2;
        const float bv0 = bias[n], bv1 = bias[n + 1];
        #pragma unroll
        for (int mt = 0; mt < 2; mt++) {
            #pragma unroll
            for (int half = 0; half < 2; half++) {
                const int r = rbase + mt * 16 + half * 8;
                *(float2*)&out[r * Dn + n] =
                    make_float2(acc[mt][j][half * 2 + 0] + bv0,
                                acc[mt][j][half * 2 + 1] + bv1);
            }
        }
    }
}

// ---------------------------------------------------------------------------
// Kernel 2: causal flash attention on tf32 tensor cores.
// BQ=128 (8 warps x 16 rows each), BK=64. Warp-local online softmax.
// K smem stride 68, V smem stride 72 (both conflict-free fragment loads).
// P C-frag -> A-frag via warp shuffles (no smem round-trip).
// ---------------------------------------------------------------------------
#define KS_STRIDE 68
#define VS_STRIDE 72
#define ATT_SMEM_WORDS (64*KS_STRIDE + 64*VS_STRIDE)   // 8960 words = 35840 B

__global__ __launch_bounds__(256) void attn_mma_kernel()
{
    __shared__ unsigned sm[ATT_SMEM_WORDS];
    unsigned* Ks = sm;                    // [64 tok][68]
    unsigned* Vs = sm + 64 * KS_STRIDE;   // [64 tok][72]
    unsigned* Qs = sm;                    // staging alias: [128 q][68] (8704 <= 8960)

    const int tid  = threadIdx.x;
    const int warp = tid >> 5, lane = tid & 31;
    const int q    = lane >> 2, l3 = lane & 3;
    const int qblk = (int)gridDim.x - 1 - (int)blockIdx.x;   // longest work first
    const int bh   = blockIdx.y;
    const int q0   = qblk * 128;

    const float* Qg = g_Q + (bh * Tn + q0) * DKn;
    const float* Kg = g_K + bh * Tn * DKn;
    const float* Vg = g_V + bh * Tn * DKn;

    // Stage Q (tf32) into smem, then pull A-fragments into registers.
    #pragma unroll
    for (int s = 0; s < 8; s++) {
        int idx = tid + 256 * s;
        int r = idx >> 4, c = (idx & 15) * 4;
        float4 v = *(const float4*)&Qg[r * DKn + c];
        *(uint4*)&Qs[r * KS_STRIDE + c] =
            make_uint4(f2tf32(v.x), f2tf32(v.y), f2tf32(v.z), f2tf32(v.w));
    }
    __syncthreads();

    unsigned Qf[8][4];
    const int wrow = warp * 16;
    #pragma unroll
    for (int j = 0; j < 8; j++) {
        int rb = (wrow + q) * KS_STRIDE + j * 8 + l3;
        Qf[j][0] = Qs[rb];
        Qf[j][1] = Qs[rb + 8 * KS_STRIDE];
        Qf[j][2] = Qs[rb + 4];
        Qf[j][3] = Qs[rb + 8 * KS_STRIDE + 4];
    }

    float O[8][4];
    #pragma unroll
    for (int j = 0; j < 8; j++)
        #pragma unroll
        for (int e = 0; e < 4; e++) O[j][e] = 0.f;
    float m_lo = -1e30f, m_hi = -1e30f, l_lo = 0.f, l_hi = 0.f;

    const int wr_lo = q0 + wrow;          // warp's min global row
    const int wr_hi = wr_lo + 15;
    const int src_lo = (lane & ~3) | (l3 >> 1);
    const int src_hi = src_lo + 2;
    const bool odd = (l3 & 1);
    const int n_kt = 2 * qblk + 2;

    for (int kt = 0; kt < n_kt; kt++) {
        const int k0 = kt * 64;
        __syncthreads();   // prior tile reads (and Q frag loads) complete
        #pragma unroll
        for (int s = 0; s < 4; s++) {
            int idx = tid + 256 * s;
            int r = idx >> 4, c = (idx & 15) * 4;
            float4 kv = *(const float4*)&Kg[(k0 + r) * DKn + c];
            *(uint4*)&Ks[r * KS_STRIDE + c] =
                make_uint4(f2tf32(kv.x), f2tf32(kv.y), f2tf32(kv.z), f2tf32(kv.w));
            float4 vv = *(const float4*)&Vg[(k0 + r) * DKn + c];
            *(uint4*)&Vs[r * VS_STRIDE + c] =
                make_uint4(f2tf32(vv.x), f2tf32(vv.y), f2tf32(vv.z), f2tf32(vv.w));
        }
        __syncthreads();

        if (k0 > wr_hi) continue;   // fully masked for this warp

        // S = Q K^T  (Q pre-scaled by 1/8)
        float S[8][4];
        #pragma unroll
        for (int j = 0; j < 8; j++)
            #pragma unroll
            for (int e = 0; e < 4; e++) S[j][e] = 0.f;

        #pragma unroll
        for (int ks = 0; ks < 8; ks++) {
            #pragma unroll
            for (int j = 0; j < 8; j++) {
                unsigned b0 = Ks[(j * 8 + q) * KS_STRIDE + ks * 8 + l3];
                unsigned b1 = Ks[(j * 8 + q) * KS_STRIDE + ks * 8 + l3 + 4];
                mma_tf32(S[j], Qf[ks], b0, b1);
            }
        }

        // causal mask
        if (k0 + 63 > wr_lo) {
            const int r0 = wr_lo + q;
            #pragma unroll
            for (int j = 0; j < 8; j++) {
                const int c = k0 + j * 8 + 2 * l3;
                if (c     > r0)     S[j][0] = -1e30f;
                if (c + 1 > r0)     S[j][1] = -1e30f;
                if (c     > r0 + 8) S[j][2] = -1e30f;
                if (c + 1 > r0 + 8) S[j][3] = -1e30f;
            }
        }

        // online softmax (rows warp-local; reduce over quad lanes)
        float mx0 = -1e30f, mx1 = -1e30f;
        #pragma unroll
        for (int j = 0; j < 8; j++) {
            mx0 = fmaxf(mx0, fmaxf(S[j][0], S[j][1]));
            mx1 = fmaxf(mx1, fmaxf(S[j][2], S[j][3]));
        }
        mx0 = fmaxf(mx0, __shfl_xor_sync(0xffffffffu, mx0, 1));
        mx0 = fmaxf(mx0, __shfl_xor_sync(0xffffffffu, mx0, 2));
        mx1 = fmaxf(mx1, __shfl_xor_sync(0xffffffffu, mx1, 1));
        mx1 = fmaxf(mx1, __shfl_xor_sync(0xffffffffu, mx1, 2));

        const float mn0 = fmaxf(m_lo, mx0);
        const float mn1 = fmaxf(m_hi, mx1);
        const float a0  = __expf(m_lo - mn0);
        const float a1  = __expf(m_hi - mn1);
        m_lo = mn0; m_hi = mn1;

        float s0 = 0.f, s1 = 0.f;
        #pragma unroll
        for (int j = 0; j < 8; j++) {
            S[j][0] = __expf(S[j][0] - mn0);
            S[j][1] = __expf(S[j][1] - mn0);
            s0 += S[j][0] + S[j][1];
            S[j][2] = __expf(S[j][2] - mn1);
            S[j][3] = __expf(S[j][3] - mn1);
            s1 += S[j][2] + S[j][3];
        }
        s0 += __shfl_xor_sync(0xffffffffu, s0, 1);
        s0 += __shfl_xor_sync(0xffffffffu, s0, 2);
        s1 += __shfl_xor_sync(0xffffffffu, s1, 1);
        s1 += __shfl_xor_sync(0xffffffffu, s1, 2);
        l_lo = l_lo * a0 + s0;
        l_hi = l_hi * a1 + s1;

        #pragma unroll
        for (int j = 0; j < 8; j++) {
            O[j][0] *= a0; O[j][1] *= a0;
            O[j][2] *= a1; O[j][3] *= a1;
        }

        // convert P to tf32 (bits kept in float regs)
        #pragma unroll
        for (int j = 0; j < 8; j++)
            #pragma unroll
            for (int e = 0; e < 4; e++)
                S[j][e] = __uint_as_float(f2tf32(S[j][e]));

        // O += P @ V : build A-frags from C-frags via shuffles
        #pragma unroll
        for (int ks = 0; ks < 8; ks++) {
            unsigned A[4];
            {
                float x0 = __shfl_sync(0xffffffffu, S[ks][0], src_lo);
                float x1 = __shfl_sync(0xffffffffu, S[ks][1], src_lo);
                A[0] = __float_as_uint(odd ? x1 : x0);
                float y0 = __shfl_sync(0xffffffffu, S[ks][2], src_lo);
                float y1 = __shfl_sync(0xffffffffu, S[ks][3], src_lo);
                A[1] = __float_as_uint(odd ? y1 : y0);
                float z0 = __shfl_sync(0xffffffffu, S[ks][0], src_hi);
                float z1 = __shfl_sync(0xffffffffu, S[ks][1], src_hi);
                A[2] = __float_as_uint(odd ? z1 : z0);
                float w0 = __shfl_sync(0xffffffffu, S[ks][2], src_hi);
                float w1 = __shfl_sync(0xffffffffu, S[ks][3], src_hi);
                A[3] = __float_as_uint(odd ? w1 : w0);
            }
            #pragma unroll
            for (int j = 0; j < 8; j++) {
                unsigned b0 = Vs[(ks * 8 + l3) * VS_STRIDE + j * 8 + q];
                unsigned b1 = Vs[(ks * 8 + l3 + 4) * VS_STRIDE + j * 8 + q];
                mma_tf32(O[j], A, b0, b1);
            }
        }
    }

    // normalize + write to g_A [B,T,D]
    const int bi = bh >> 4;
    const int h  = bh & 15;
    const float inv0 = 1.f / l_lo;
    const float inv1 = 1.f / l_hi;
    const int t0 = q0 + wrow + q;
    float* outp = g_A + (bi * Tn + t0) * Dn + h * DKn;
    #pragma unroll
    for (int j = 0; j < 8; j++) {
        *(float2*)&outp[j * 8 + 2 * l3] =
            make_float2(O[j][0] * inv0, O[j][1] * inv0);
        *(float2*)&outp[8 * Dn + j * 8 + 2 * l3] =
            make_float2(O[j][2] * inv1, O[j][3] * inv1);
    }
}

// ---------------------------------------------------------------------------
extern "C" void kernel_launch(void* const* d_in, const int* in_sizes, int n_in,
                              void* d_out, int out_size)
{
    const float* x    = (const float*)d_in[0];
    const float* wqkv = (const float*)d_in[1];
    const float* bqkv = (const float*)d_in[2];
    const float* wout = (const float*)d_in[3];
    const float* bout = (const float*)d_in[4];
    const float* fc   = (const float*)d_in[5];
    const float* fs   = (const float*)d_in[6];
    float* out = (float*)d_out;

    qkv_mma_kernel<<<dim3(Nqkv/128, Mn/128), 256>>>(x, wqkv, bqkv, fc, fs);
    attn_mma_kernel<<<dim3(Tn/128, Bn*Hn), 256>>>();
    proj_mma_kernel<<<dim3(Dn/128, Mn/128), 256>>>(wout, bout, out);
}